// round 16
// baseline (speedup 1.0000x reference)
#include <cuda_runtime.h>
#include <cuda_bf16.h>
#include <cuda_fp16.h>
#include <cuda_fp8.h>
#include <math.h>
#include <stdint.h>

#define NROWS 8192
#define HALF_N 4096
#define DIM 512                   // elements (= bytes in fp8)
#define NT 64                     // 8192/128 tiles per dim
#define NTRI (NT * (NT + 1) / 2)  // 2080 upper-triangle tiles
#define BK 128                    // fp8 elements per k-chunk (= 128 bytes)
#define PITCHB 144                // smem row pitch bytes (128 data + 16 pad)
#define TILE_B (128 * PITCHB)     // 18432 B per operand tile
#define STAGE_B (2 * TILE_B)      // 36864 B per stage (A+B)
#define NSTAGE 2
#define SMEM_DYN (NSTAGE * STAGE_B)   // 73728 B -> 3 CTAs/SM
#define NITER (DIM / BK)          // 4
#define QSCALE 16.0f              // fp8 quantization pre-scale
// base-2 logit: l2 = acc * (10 * log2(e) / QSCALE^2)
#define LS2 (14.426950408889634f / (QSCALE * QSCALE))
#define LN2F 0.6931471805599453f

// ---------------- device scratch (allocation-free rule) ----------------
__device__ __align__(256) uint8_t g_unitq[NROWS * DIM];   // 4 MB fp8(e4m3) units
__device__ float g_part[NT * NROWS];
__device__ float g_pos[NROWS];                            // base-2 pos logits
__device__ float g_blk[NT];
__device__ unsigned int g_done;                           // zero-init; self-reset

__device__ __forceinline__ uint32_t smem_u32(const void* p) {
    uint32_t a;
    asm("{ .reg .u64 t; cvta.to.shared.u64 t, %1; cvt.u32.u64 %0, t; }"
        : "=r"(a) : "l"(p));
    return a;
}

__device__ __forceinline__ uint32_t ex2_f16x2(uint32_t x) {
    uint32_t r;
    asm("ex2.approx.f16x2 %0, %1;" : "=r"(r) : "r"(x));
    return r;
}

#define CP_ASYNC16(dst, src) \
    asm volatile("cp.async.cg.shared.global [%0], [%1], 16;" :: "r"(dst), "l"(src))
#define CP_COMMIT() asm volatile("cp.async.commit_group;" ::: "memory")
#define CP_WAIT(n)  asm volatile("cp.async.wait_group %0;" :: "n"(n) : "memory")

#define LDMATRIX_X4(r0, r1, r2, r3, addr) \
    asm volatile("ldmatrix.sync.aligned.m8n8.x4.shared.b16 {%0,%1,%2,%3}, [%4];" \
                 : "=r"(r0), "=r"(r1), "=r"(r2), "=r"(r3) : "r"(addr))

// fp8 e4m3 MMA with FP16 accumulators: m16n8k32, 2x b32 acc regs (half2 pairs)
#define MMA_FP8_H(c, a, b0, b1) \
    asm volatile("mma.sync.aligned.m16n8k32.row.col.f16.e4m3.e4m3.f16 " \
                 "{%0,%1}, {%2,%3,%4,%5}, {%6,%7}, {%0,%1};" \
                 : "+r"((c)[0]), "+r"((c)[1]) \
                 : "r"((a)[0]), "r"((a)[1]), "r"((a)[2]), "r"((a)[3]), \
                   "r"(b0), "r"(b1))

// ---------------------------------------------------------------------------
// 1) Normalize + fp8 quantize (x QSCALE): one WARP per row, no block sync.
//    Lane handles 16 contiguous floats (4 x float4, MLP=4); shfl-only reduce.
// ---------------------------------------------------------------------------
__global__ __launch_bounds__(256)
void normalize_kernel(const float* __restrict__ z1, const float* __restrict__ z2) {
    int wid = threadIdx.x >> 5;
    int lane = threadIdx.x & 31;
    int row = blockIdx.x * 8 + wid;
    const float* src = (row < HALF_N) ? (z1 + (size_t)row * DIM)
                                      : (z2 + (size_t)(row - HALF_N) * DIM);
    float4 v[4];
#pragma unroll
    for (int i = 0; i < 4; i++)
        v[i] = *(const float4*)(src + lane * 16 + i * 4);

    float ss = 0.f;
#pragma unroll
    for (int i = 0; i < 4; i++)
        ss += v[i].x * v[i].x + v[i].y * v[i].y + v[i].z * v[i].z + v[i].w * v[i].w;
#pragma unroll
    for (int o = 16; o > 0; o >>= 1) ss += __shfl_xor_sync(0xffffffffu, ss, o);

    float inv = QSCALE / fmaxf(sqrtf(ss), 1e-8f);
    uint32_t pk[4];
#pragma unroll
    for (int i = 0; i < 4; i++) {
        __nv_fp8x4_e4m3 q(make_float4(v[i].x * inv, v[i].y * inv,
                                      v[i].z * inv, v[i].w * inv));
        pk[i] = *(uint32_t*)&q;
    }
    *(uint4*)(g_unitq + (size_t)row * DIM + lane * 16) =
        make_uint4(pk[0], pk[1], pk[2], pk[3]);
}

// ---------------------------------------------------------------------------
// 2) fp8 QMMA GEMM tile (128x128, K=512, BK=128 bytes, 2-stage cp.async,
//    f16 accumulators, 3 CTAs/SM, FULLY UNROLLED k-loop so every smem address
//    is base-reg + compile-time constant), upper-triangle tiles only.
//    Off-diagonal tiles emit BOTH row and col sums (S = S^T). Positive pair
//    sits on the local diagonal of bj==bi+32 tiles; self-mask on bi==bj.
//    Finalize folded into the tail (last 64 arrivals).
//    8 warps: warp_m = wid&1 (2 x 64 rows), warp_n = wid>>1 (4 x 32 cols).
// ---------------------------------------------------------------------------
__global__ __launch_bounds__(256, 3)
void gemm_exp_kernel(float* __restrict__ out) {
    // triangular decode: block b -> (bi, bj), bi <= bj, bi-major
    int b = blockIdx.x;
    float tf = (float)NT + 0.5f;
    int bi = (int)(tf - sqrtf(fmaxf(tf * tf - 2.0f * (float)b, 0.f)));
    while ((bi + 1) * NT - ((bi + 1) * bi) / 2 <= b) bi++;
    while (bi * NT - (bi * (bi - 1)) / 2 > b) bi--;
    int bj = bi + (b - (bi * NT - (bi * (bi - 1)) / 2));

    extern __shared__ __align__(128) char sm[];
    uint32_t sb = smem_u32(sm);

    int t = threadIdx.x;
    int lane = t & 31, wid = t >> 5;
    int warp_m = wid & 1, warp_n = wid >> 1;
    int R0 = bi * 128, C0 = bj * 128;
    bool offdiag = (bi != bj);
    bool ispos = (bj == bi + 32);

    // f16 accumulators: [i][f][h] is a half2 = cols {e0,e1} of row-half h
    uint32_t hacc[4][4][2];
#pragma unroll
    for (int i = 0; i < 4; i++)
#pragma unroll
        for (int f = 0; f < 4; f++) {
            hacc[i][f][0] = 0u;
            hacc[i][f][1] = 0u;
        }

    // per-thread smem fragment base offsets (b16 view: 1 slot = 2 fp8)
    uint32_t aoff = (uint32_t)((warp_m * 64 + (lane & 7) + ((lane >> 3) & 1) * 8)
                               * PITCHB + ((lane >> 4) * 8) * 2);
    uint32_t boff = (uint32_t)((warp_n * 32 + (lane & 7) + (lane >> 4) * 8)
                               * PITCHB + (((lane >> 3) & 1) * 8) * 2);

    // per-thread cp.async bases: thread covers rows (t>>3)+l*32, chunk (t&7)
    uint32_t ld_dst = sb + (uint32_t)((t >> 3) * PITCHB + (t & 7) * 16);
    const uint8_t* ga = g_unitq + (size_t)(R0 + (t >> 3)) * DIM + (t & 7) * 16;
    const uint8_t* gb = g_unitq + (size_t)(C0 + (t >> 3)) * DIM + (t & 7) * 16;

#define LOAD_STAGE(stg, kk)                                                   \
    do {                                                                      \
        _Pragma("unroll")                                                     \
        for (int l = 0; l < 4; l++) {                                         \
            CP_ASYNC16(ld_dst + (stg) * STAGE_B + l * 32 * PITCHB,            \
                       ga + (kk) + (size_t)l * 32 * DIM);                     \
            CP_ASYNC16(ld_dst + (stg) * STAGE_B + TILE_B + l * 32 * PITCHB,   \
                       gb + (kk) + (size_t)l * 32 * DIM);                     \
        }                                                                     \
        CP_COMMIT();                                                          \
    } while (0)

    LOAD_STAGE(0, 0);

#pragma unroll
    for (int it = 0; it < NITER; it++) {
        CP_WAIT(0);
        __syncthreads();
        if (it < NITER - 1) LOAD_STAGE((it + 1) & 1, (it + 1) * BK);
        uint32_t ab = sb + (it & 1) * STAGE_B + aoff;
        uint32_t bb = sb + (it & 1) * STAGE_B + TILE_B + boff;

#pragma unroll
        for (int ks = 0; ks < 4; ks++) {
            uint32_t a[4][4], bfr[2][4];
#pragma unroll
            for (int i = 0; i < 4; i++)
                LDMATRIX_X4(a[i][0], a[i][1], a[i][2], a[i][3],
                            ab + (uint32_t)(i * 16 * PITCHB + ks * 32));
#pragma unroll
            for (int nb = 0; nb < 2; nb++)
                LDMATRIX_X4(bfr[nb][0], bfr[nb][1], bfr[nb][2], bfr[nb][3],
                            bb + (uint32_t)(nb * 16 * PITCHB + ks * 32));
#pragma unroll
            for (int i = 0; i < 4; i++)
#pragma unroll
                for (int f = 0; f < 4; f++)
                    MMA_FP8_H(hacc[i][f], a[i], bfr[f >> 1][(f & 1) * 2],
                              bfr[f >> 1][(f & 1) * 2 + 1]);
        }
    }
    __syncthreads();   // all compute done; smem now reusable for reduction

    // Epilogue in half2. f16 acc frag: reg h -> row (lane>>2) + 8*h,
    // half .x/.y -> cols 2*(lane&3) + {0,1}. Base-2 logits via ex2.f16x2.
    int g = lane >> 2, tq = lane & 3;
    float* red  = (float*)sm;                // 128 rows x 4 warp_n   (2 KB)
    float* redC = (float*)(sm + 2048);       // 128 cols x 2 warp_m   (1 KB)
    const __half2 ls2h2 = __float2half2_rn(LS2);
    int col_base = warp_n * 32 + tq * 2;     // + f*8; pair covers {c, c+1}
    float rsum[4][2];
    float csum[4][2];
#pragma unroll
    for (int f = 0; f < 4; f++) { csum[f][0] = 0.f; csum[f][1] = 0.f; }

#pragma unroll
    for (int i = 0; i < 4; i++) {
#pragma unroll
        for (int h = 0; h < 2; h++) {
            int rl = warp_m * 64 + i * 16 + g + 8 * h;   // local row
            float s = 0.f;
#pragma unroll
            for (int f = 0; f < 4; f++) {
                __half2 l2 = __hmul2(*(__half2*)&hacc[i][f][h], ls2h2);
                int c0 = col_base + f * 8;
                if (ispos) {                 // positive sits on local diagonal
                    if (c0 == rl) {
                        float pv = __low2float(l2);
                        g_pos[R0 + rl] = pv;  g_pos[C0 + c0] = pv;
                    } else if (c0 + 1 == rl) {
                        float pv = __high2float(l2);
                        g_pos[R0 + rl] = pv;  g_pos[C0 + c0 + 1] = pv;
                    }
                }
                if (!offdiag) {              // self-mask on local diagonal
                    if (c0 == rl)
                        l2 = __halves2half2(__ushort_as_half(0xFC00),
                                            __high2half(l2));
                    else if (c0 + 1 == rl)
                        l2 = __halves2half2(__low2half(l2),
                                            __ushort_as_half(0xFC00));
                }
                uint32_t ex = ex2_f16x2(*(uint32_t*)&l2);
                float2 f2 = __half22float2(*(__half2*)&ex);
                s += f2.x + f2.y;
                csum[f][0] += f2.x;
                csum[f][1] += f2.y;
            }
            rsum[i][h] = s;
        }
    }
    // row-sum reduction over the 4 column-quads within each warp
#pragma unroll
    for (int i = 0; i < 4; i++)
#pragma unroll
        for (int h = 0; h < 2; h++) {
            float v = rsum[i][h];
            v += __shfl_xor_sync(0xffffffffu, v, 1);
            v += __shfl_xor_sync(0xffffffffu, v, 2);
            if (tq == 0)
                red[(warp_m * 64 + i * 16 + g + 8 * h) * 4 + warp_n] = v;
        }
    // col-sum reduction over the 8 row-groups within each warp
    if (offdiag) {
#pragma unroll
        for (int f = 0; f < 4; f++)
#pragma unroll
            for (int e = 0; e < 2; e++) {
                float v = csum[f][e];
                v += __shfl_xor_sync(0xffffffffu, v, 4);
                v += __shfl_xor_sync(0xffffffffu, v, 8);
                v += __shfl_xor_sync(0xffffffffu, v, 16);
                if (g == 0)
                    redC[(warp_n * 32 + f * 8 + tq * 2 + e) * 2 + warp_m] = v;
            }
    }
    __syncthreads();
    if (t < 128) {
        float s = red[t * 4] + red[t * 4 + 1] + red[t * 4 + 2] + red[t * 4 + 3];
        g_part[(size_t)bj * NROWS + R0 + t] = s;              // rows of tile bi
        if (offdiag)
            g_part[(size_t)bi * NROWS + C0 + t] = redC[t * 2] + redC[t * 2 + 1];
    }

    // ---- embedded finalize: last 64 arrivals each reduce one 128-row slice ----
    __threadfence();
    __syncthreads();
    __shared__ unsigned int s_prev;
    if (t == 0) s_prev = atomicAdd(&g_done, 1u);
    __syncthreads();
    unsigned int prev = s_prev;
    if (prev < NTRI - NT) return;            // not a finalizer

    int slice = (int)(NTRI - 1u - prev);     // 0..63, unique per finalizer
    if (t == 0) {
        while (*(volatile unsigned int*)&g_done < (unsigned int)NTRI)
            __nanosleep(64);
        __threadfence();
    }
    __syncthreads();

    // finalize1: rows slice*128 .. +127 (threads 0..127)
    float v = 0.f;
    if (t < 128) {
        int r = slice * 128 + t;
        float rs = 0.f;
#pragma unroll 8
        for (int c = 0; c < NT; c++) rs += g_part[(size_t)c * NROWS + r];
        v = (log2f(rs) - g_pos[r]) * LN2F;
    }
#pragma unroll
    for (int o = 16; o > 0; o >>= 1) v += __shfl_xor_sync(0xffffffffu, v, o);
    float* ws = red;                          // reuse smem
    if (t < 128 && (t & 31) == 0) ws[t >> 5] = v;
    __syncthreads();

    __shared__ unsigned int is_last;
    if (t == 0) {
        g_blk[slice] = ws[0] + ws[1] + ws[2] + ws[3];
        __threadfence();
        unsigned int p2 = atomicAdd(&g_done, 1u);
        is_last = (p2 == (unsigned int)(NTRI + NT - 1)) ? 1u : 0u;
    }
    __syncthreads();
    if (is_last) {
        if (t == 0) __threadfence();          // acquire g_blk
        __syncthreads();
        if (t < 32) {
            float sum = g_blk[t] + g_blk[t + 32];   // fixed order -> deterministic
#pragma unroll
            for (int o = 16; o > 0; o >>= 1)
                sum += __shfl_xor_sync(0xffffffffu, sum, o);
            if (t == 0) {
                out[0] = sum / (float)NROWS;
                g_done = 0u;                        // reset for graph replay
            }
        }
    }
}

extern "C" void kernel_launch(void* const* d_in, const int* in_sizes, int n_in,
                              void* d_out, int out_size) {
    const float* z1 = (const float*)d_in[0];
    const float* z2 = (const float*)d_in[1];

    static int configured = 0;
    if (!configured) {
        cudaFuncSetAttribute(gemm_exp_kernel,
                             cudaFuncAttributeMaxDynamicSharedMemorySize, SMEM_DYN);
        configured = 1;
    }

    normalize_kernel<<<NROWS / 8, 256>>>(z1, z2);
    gemm_exp_kernel<<<NTRI, 256, SMEM_DYN>>>((float*)d_out);
}

// round 17
// speedup vs baseline: 1.0459x; 1.0459x over previous
#include <cuda_runtime.h>
#include <cuda_bf16.h>
#include <cuda_fp16.h>
#include <cuda_fp8.h>
#include <math.h>
#include <stdint.h>

#define NROWS 8192
#define HALF_N 4096
#define DIM 512                   // elements (= bytes in fp8)
#define NT 64                     // 8192/128 tiles per dim
#define NTRI (NT * (NT + 1) / 2)  // 2080 upper-triangle tiles
#define BK 128                    // fp8 elements per k-chunk (= 128 bytes)
#define PITCHB 144                // smem row pitch bytes (128 data + 16 pad)
#define TILE_B (128 * PITCHB)     // 18432 B per operand tile
#define STAGE_B (2 * TILE_B)      // 36864 B per stage (A+B)
#define NSTAGE 2
#define SMEM_DYN (NSTAGE * STAGE_B)   // 73728 B -> 3 CTAs/SM
#define NITER (DIM / BK)          // 4
#define QSCALE 16.0f              // fp8 quantization pre-scale
// base-2 logit: l2 = acc * (10 * log2(e) / QSCALE^2)
#define LS2 (14.426950408889634f / (QSCALE * QSCALE))
#define LN2F 0.6931471805599453f

// ---------------- device scratch (allocation-free rule) ----------------
__device__ __align__(256) uint8_t g_unitq[NROWS * DIM];   // 4 MB fp8(e4m3) units
__device__ float g_part[NT * NROWS];
__device__ float g_pos[NROWS];                            // base-2 pos logits
__device__ float g_blk[NT];
__device__ unsigned int g_done;                           // zero-init; self-reset

__device__ __forceinline__ uint32_t smem_u32(const void* p) {
    uint32_t a;
    asm("{ .reg .u64 t; cvta.to.shared.u64 t, %1; cvt.u32.u64 %0, t; }"
        : "=r"(a) : "l"(p));
    return a;
}

__device__ __forceinline__ uint32_t ex2_f16x2(uint32_t x) {
    uint32_t r;
    asm("ex2.approx.f16x2 %0, %1;" : "=r"(r) : "r"(x));
    return r;
}

#define CP_ASYNC16(dst, src) \
    asm volatile("cp.async.cg.shared.global [%0], [%1], 16;" :: "r"(dst), "l"(src))
#define CP_COMMIT() asm volatile("cp.async.commit_group;" ::: "memory")
#define CP_WAIT(n)  asm volatile("cp.async.wait_group %0;" :: "n"(n) : "memory")

#define LDMATRIX_X4(r0, r1, r2, r3, addr) \
    asm volatile("ldmatrix.sync.aligned.m8n8.x4.shared.b16 {%0,%1,%2,%3}, [%4];" \
                 : "=r"(r0), "=r"(r1), "=r"(r2), "=r"(r3) : "r"(addr))

// fp8 e4m3 MMA with FP16 accumulators: m16n8k32, 2x b32 acc regs (half2 pairs)
#define MMA_FP8_H(c, a, b0, b1) \
    asm volatile("mma.sync.aligned.m16n8k32.row.col.f16.e4m3.e4m3.f16 " \
                 "{%0,%1}, {%2,%3,%4,%5}, {%6,%7}, {%0,%1};" \
                 : "+r"((c)[0]), "+r"((c)[1]) \
                 : "r"((a)[0]), "r"((a)[1]), "r"((a)[2]), "r"((a)[3]), \
                   "r"(b0), "r"(b1))

// ---------------------------------------------------------------------------
// 1) Normalize + fp8 quantize (x QSCALE): one WARP per row, lane-major
//    element mapping so each warp LDG/STG touches minimal cache lines:
//    v[i] = row[i*128 + lane*4] -> warp-LDG covers 512B contiguous (nL=4).
//    Stores: 4 x STG.32, each a full 128B line across the warp.
// ---------------------------------------------------------------------------
__global__ __launch_bounds__(256)
void normalize_kernel(const float* __restrict__ z1, const float* __restrict__ z2) {
    int wid = threadIdx.x >> 5;
    int lane = threadIdx.x & 31;
    int row = blockIdx.x * 8 + wid;
    const float* src = (row < HALF_N) ? (z1 + (size_t)row * DIM)
                                      : (z2 + (size_t)(row - HALF_N) * DIM);
    float4 v[4];
#pragma unroll
    for (int i = 0; i < 4; i++)
        v[i] = *(const float4*)(src + i * 128 + lane * 4);

    float ss = 0.f;
#pragma unroll
    for (int i = 0; i < 4; i++)
        ss += v[i].x * v[i].x + v[i].y * v[i].y + v[i].z * v[i].z + v[i].w * v[i].w;
#pragma unroll
    for (int o = 16; o > 0; o >>= 1) ss += __shfl_xor_sync(0xffffffffu, ss, o);

    float inv = QSCALE / fmaxf(sqrtf(ss), 1e-8f);
#pragma unroll
    for (int i = 0; i < 4; i++) {
        __nv_fp8x4_e4m3 q(make_float4(v[i].x * inv, v[i].y * inv,
                                      v[i].z * inv, v[i].w * inv));
        *(uint32_t*)(g_unitq + (size_t)row * DIM + i * 128 + lane * 4) =
            *(uint32_t*)&q;
    }
}

// ---------------------------------------------------------------------------
// 2) fp8 QMMA GEMM tile (128x128, K=512, BK=128 bytes, 2-stage cp.async,
//    f16 accumulators, 3 CTAs/SM), upper-triangle tiles only. Off-diagonal
//    tiles emit BOTH row-sum and col-sum partials (S = S^T). Positive pair
//    sits on the local diagonal of bj==bi+32 tiles; self-mask on bi==bj.
//    The finalize is folded into the tail: the last 64 arriving CTAs each
//    reduce one deterministic 128-row slice; the 64th writes the output.
//    8 warps: warp_m = wid&1 (2 x 64 rows), warp_n = wid>>1 (4 x 32 cols).
// ---------------------------------------------------------------------------
__device__ __forceinline__ void load_stage(uint32_t sbase,
                                           const uint8_t* __restrict__ g,
                                           int R0, int C0, int kk, int t) {
#pragma unroll
    for (int l = 0; l < 4; l++) {          // A tile: 128 rows x 8 chunks of 16B
        int idx = t + l * 256;
        int row = idx >> 3, c4 = idx & 7;
        uint32_t dst = sbase + (uint32_t)(row * PITCHB + c4 * 16);
        const void* src = g + (size_t)(R0 + row) * DIM + kk + c4 * 16;
        CP_ASYNC16(dst, src);
    }
#pragma unroll
    for (int l = 0; l < 4; l++) {          // B tile
        int idx = t + l * 256;
        int row = idx >> 3, c4 = idx & 7;
        uint32_t dst = sbase + (uint32_t)(TILE_B + row * PITCHB + c4 * 16);
        const void* src = g + (size_t)(C0 + row) * DIM + kk + c4 * 16;
        CP_ASYNC16(dst, src);
    }
}

__global__ __launch_bounds__(256, 3)
void gemm_exp_kernel(float* __restrict__ out) {
    // triangular decode: block b -> (bi, bj), bi <= bj, bi-major
    int b = blockIdx.x;
    float tf = (float)NT + 0.5f;
    int bi = (int)(tf - sqrtf(fmaxf(tf * tf - 2.0f * (float)b, 0.f)));
    while ((bi + 1) * NT - ((bi + 1) * bi) / 2 <= b) bi++;
    while (bi * NT - (bi * (bi - 1)) / 2 > b) bi--;
    int bj = bi + (b - (bi * NT - (bi * (bi - 1)) / 2));

    extern __shared__ __align__(128) char sm[];
    uint32_t sb = smem_u32(sm);

    int t = threadIdx.x;
    int lane = t & 31, wid = t >> 5;
    int warp_m = wid & 1, warp_n = wid >> 1;
    int R0 = bi * 128, C0 = bj * 128;
    bool offdiag = (bi != bj);
    bool ispos = (bj == bi + 32);

    // f16 accumulators: [i][f][h] is a half2 = cols {e0,e1} of row-half h
    uint32_t hacc[4][4][2];
#pragma unroll
    for (int i = 0; i < 4; i++)
#pragma unroll
        for (int f = 0; f < 4; f++) {
            hacc[i][f][0] = 0u;
            hacc[i][f][1] = 0u;
        }

    // fragment addresses in b16-view units (1 b16 slot = 2 fp8 along k)
    int a_row = warp_m * 64 + (lane & 7) + ((lane >> 3) & 1) * 8; // + i*16
    int a_col8 = (lane >> 4) * 8;                                 // + k0 (b16 units)
    int b_row = warp_n * 32 + (lane & 7) + (lane >> 4) * 8;       // + nb*16
    int b_col8 = ((lane >> 3) & 1) * 8;                           // + k0 (b16 units)

    // prime stage 0 of the 2-stage ring
    load_stage(sb, g_unitq, R0, C0, 0, t);
    CP_COMMIT();

#pragma unroll 1
    for (int it = 0; it < NITER; it++) {
        CP_WAIT(0);
        __syncthreads();
        if (it < NITER - 1) {
            load_stage(sb + ((it + 1) & 1) * STAGE_B, g_unitq, R0, C0,
                       (it + 1) * BK, t);
            CP_COMMIT();
        }
        uint32_t ab = sb + (it & 1) * STAGE_B;
        uint32_t bb = ab + TILE_B;

#pragma unroll
        for (int ks = 0; ks < 4; ks++) {
            int k0 = ks * 16;              // b16 units: 16 slots = 32 fp8 per mma
            uint32_t a[4][4], bfr[2][4];
#pragma unroll
            for (int i = 0; i < 4; i++) {
                uint32_t addr = ab + (uint32_t)((a_row + i * 16) * PITCHB +
                                                (a_col8 + k0) * 2);
                LDMATRIX_X4(a[i][0], a[i][1], a[i][2], a[i][3], addr);
            }
#pragma unroll
            for (int nb = 0; nb < 2; nb++) {
                uint32_t addr = bb + (uint32_t)((b_row + nb * 16) * PITCHB +
                                                (b_col8 + k0) * 2);
                LDMATRIX_X4(bfr[nb][0], bfr[nb][1], bfr[nb][2], bfr[nb][3], addr);
            }
#pragma unroll
            for (int i = 0; i < 4; i++)
#pragma unroll
                for (int f = 0; f < 4; f++)
                    MMA_FP8_H(hacc[i][f], a[i], bfr[f >> 1][(f & 1) * 2],
                              bfr[f >> 1][(f & 1) * 2 + 1]);
        }
    }
    __syncthreads();   // all compute done; smem now reusable for reduction

    // Epilogue in half2. f16 acc frag: reg h -> row (lane>>2) + 8*h,
    // half .x/.y -> cols 2*(lane&3) + {0,1}. Base-2 logits via ex2.f16x2.
    int g = lane >> 2, tq = lane & 3;
    float* red  = (float*)sm;                // 128 rows x 4 warp_n   (2 KB)
    float* redC = (float*)(sm + 2048);       // 128 cols x 2 warp_m   (1 KB)
    const __half2 ls2h2 = __float2half2_rn(LS2);
    int col_base = warp_n * 32 + tq * 2;     // + f*8; pair covers {c, c+1}
    float rsum[4][2];
    float csum[4][2];
#pragma unroll
    for (int f = 0; f < 4; f++) { csum[f][0] = 0.f; csum[f][1] = 0.f; }

#pragma unroll
    for (int i = 0; i < 4; i++) {
#pragma unroll
        for (int h = 0; h < 2; h++) {
            int rl = warp_m * 64 + i * 16 + g + 8 * h;   // local row
            float s = 0.f;
#pragma unroll
            for (int f = 0; f < 4; f++) {
                __half2 l2 = __hmul2(*(__half2*)&hacc[i][f][h], ls2h2);
                int c0 = col_base + f * 8;
                if (ispos) {                 // positive sits on local diagonal
                    if (c0 == rl) {
                        float pv = __low2float(l2);
                        g_pos[R0 + rl] = pv;  g_pos[C0 + c0] = pv;
                    } else if (c0 + 1 == rl) {
                        float pv = __high2float(l2);
                        g_pos[R0 + rl] = pv;  g_pos[C0 + c0 + 1] = pv;
                    }
                }
                if (!offdiag) {              // self-mask on local diagonal
                    if (c0 == rl)
                        l2 = __halves2half2(__ushort_as_half(0xFC00),
                                            __high2half(l2));
                    else if (c0 + 1 == rl)
                        l2 = __halves2half2(__low2half(l2),
                                            __ushort_as_half(0xFC00));
                }
                uint32_t ex = ex2_f16x2(*(uint32_t*)&l2);
                float2 f2 = __half22float2(*(__half2*)&ex);
                s += f2.x + f2.y;
                csum[f][0] += f2.x;
                csum[f][1] += f2.y;
            }
            rsum[i][h] = s;
        }
    }
    // row-sum reduction over the 4 column-quads within each warp
#pragma unroll
    for (int i = 0; i < 4; i++)
#pragma unroll
        for (int h = 0; h < 2; h++) {
            float v = rsum[i][h];
            v += __shfl_xor_sync(0xffffffffu, v, 1);
            v += __shfl_xor_sync(0xffffffffu, v, 2);
            if (tq == 0)
                red[(warp_m * 64 + i * 16 + g + 8 * h) * 4 + warp_n] = v;
        }
    // col-sum reduction over the 8 row-groups within each warp
    if (offdiag) {
#pragma unroll
        for (int f = 0; f < 4; f++)
#pragma unroll
            for (int e = 0; e < 2; e++) {
                float v = csum[f][e];
                v += __shfl_xor_sync(0xffffffffu, v, 4);
                v += __shfl_xor_sync(0xffffffffu, v, 8);
                v += __shfl_xor_sync(0xffffffffu, v, 16);
                if (g == 0)
                    redC[(warp_n * 32 + f * 8 + tq * 2 + e) * 2 + warp_m] = v;
            }
    }
    __syncthreads();
    if (t < 128) {
        float s = red[t * 4] + red[t * 4 + 1] + red[t * 4 + 2] + red[t * 4 + 3];
        g_part[(size_t)bj * NROWS + R0 + t] = s;              // rows of tile bi
        if (offdiag)
            g_part[(size_t)bi * NROWS + C0 + t] = redC[t * 2] + redC[t * 2 + 1];
    }

    // ---- embedded finalize: last 64 arrivals each reduce one 128-row slice ----
    __threadfence();
    __syncthreads();
    __shared__ unsigned int s_prev;
    if (t == 0) s_prev = atomicAdd(&g_done, 1u);
    __syncthreads();
    unsigned int prev = s_prev;
    if (prev < NTRI - NT) return;            // not a finalizer

    int slice = (int)(NTRI - 1u - prev);     // 0..63, unique per finalizer
    if (t == 0) {
        while (*(volatile unsigned int*)&g_done < (unsigned int)NTRI)
            __nanosleep(64);
        __threadfence();
    }
    __syncthreads();

    // finalize1: rows slice*128 .. +127 (threads 0..127)
    float v = 0.f;
    if (t < 128) {
        int r = slice * 128 + t;
        float rs = 0.f;
#pragma unroll 8
        for (int c = 0; c < NT; c++) rs += g_part[(size_t)c * NROWS + r];
        v = (log2f(rs) - g_pos[r]) * LN2F;
    }
#pragma unroll
    for (int o = 16; o > 0; o >>= 1) v += __shfl_xor_sync(0xffffffffu, v, o);
    float* ws = red;                          // reuse smem
    if (t < 128 && (t & 31) == 0) ws[t >> 5] = v;
    __syncthreads();

    __shared__ unsigned int is_last;
    if (t == 0) {
        g_blk[slice] = ws[0] + ws[1] + ws[2] + ws[3];
        __threadfence();
        unsigned int p2 = atomicAdd(&g_done, 1u);
        is_last = (p2 == (unsigned int)(NTRI + NT - 1)) ? 1u : 0u;
    }
    __syncthreads();
    if (is_last) {
        if (t == 0) __threadfence();          // acquire g_blk
        __syncthreads();
        if (t < 32) {
            float sum = g_blk[t] + g_blk[t + 32];   // fixed order -> deterministic
#pragma unroll
            for (int o = 16; o > 0; o >>= 1)
                sum += __shfl_xor_sync(0xffffffffu, sum, o);
            if (t == 0) {
                out[0] = sum / (float)NROWS;
                g_done = 0u;                        // reset for graph replay
            }
        }
    }
}

extern "C" void kernel_launch(void* const* d_in, const int* in_sizes, int n_in,
                              void* d_out, int out_size) {
    const float* z1 = (const float*)d_in[0];
    const float* z2 = (const float*)d_in[1];

    static int configured = 0;
    if (!configured) {
        cudaFuncSetAttribute(gemm_exp_kernel,
                             cudaFuncAttributeMaxDynamicSharedMemorySize, SMEM_DYN);
        configured = 1;
    }

    normalize_kernel<<<NROWS / 8, 256>>>(z1, z2);
    gemm_exp_kernel<<<NTRI, 256, SMEM_DYN>>>((float*)d_out);
}